// round 5
// baseline (speedup 1.0000x reference)
#include <cuda_runtime.h>
#include <math.h>

// ROI pooling, single ROI, POOL = 7x7, SCALE_FACTOR = 1.0
// img: (1, 512, 512, 256) fp32 NHWC   -> d_in[0]
// roi: (1, 5) fp32 [_, x_min, y_min, x_max, y_max] -> d_in[1]
// out: (1, 256, 7, 7) fp32            -> d_out
//
// out[c*49 + py*7 + px] = img[((iy*512) + ix)*256 + c]
// with iy = clip(y_min + floor(py * (h/7)), y_min, y_max), same for ix.
//
// Index math mirrors the JAX reference in fp32:
//   jnp.round -> rintf (round-half-to-even under default RN),
//   h/7 computed once in fp32, py*(h/7) in fp32, floorf.

#define IMG_W 256          // channels (innermost)
#define IMG_COLS 512
#define PH 7
#define PW 7

__global__ __launch_bounds__(256)
void roi_pool_kernel(const float* __restrict__ img,
                     const float* __restrict__ roi,
                     float* __restrict__ out)
{
    const int p  = blockIdx.x;        // pooled pixel 0..48
    const int py = p / PW;
    const int px = p % PW;
    const int c  = threadIdx.x;       // channel 0..255

    // SCALE_FACTOR == 1.0, so r == roi. rintf == round-half-to-even.
    const int x_min = (int)rintf(roi[1]);
    const int y_min = (int)rintf(roi[2]);
    const int x_max = (int)rintf(roi[3]);
    const int y_max = (int)rintf(roi[4]);

    const float h = (float)(y_max - y_min + 1);
    const float w = (float)(x_max - x_min + 1);

    int iy = y_min + (int)floorf((float)py * (h / 7.0f));
    int ix = x_min + (int)floorf((float)px * (w / 7.0f));
    iy = min(max(iy, y_min), y_max);
    ix = min(max(ix, x_min), x_max);

    // Coalesced 1KB read of the pixel's channel vector per block.
    const float v = img[((iy * IMG_COLS) + ix) * IMG_W + c];

    // NCHW output: stride-49 scatter per thread; merged in L2 (output = 50KB).
    out[c * (PH * PW) + p] = v;
}

extern "C" void kernel_launch(void* const* d_in, const int* in_sizes, int n_in,
                              void* d_out, int out_size)
{
    const float* img = (const float*)d_in[0];
    const float* roi = (const float*)d_in[1];
    float* out = (float*)d_out;

    roi_pool_kernel<<<PH * PW, 256>>>(img, roi, out);
}